// round 14
// baseline (speedup 1.0000x reference)
#include <cuda_runtime.h>
#include <cuda_fp16.h>
#include <math.h>

#define NC   6
#define NH   8
#define NL   3
#define NPT  8
#define CDIM 256
#define DDIM 32
#define NQ   6400
#define STOT 14784   // 64*176 + 32*88 + 16*44

// ---------------- scratch (device globals; no allocations allowed) ----------
__device__ float  g_coor[NC * NQ * 2];
__device__ float  g_mask[NC * NQ];
__device__ float  g_off [NQ * 384];
__device__ float  g_attn[NQ * 192];
__device__ float  g_slots[NQ * CDIM];
__device__ __align__(16) __half g_WhT [CDIM * CDIM];        // W_val^T [n][k]
__device__ __align__(16) __half g_WoaT[576 * CDIM];         // [W_off|W_attn]^T [n][k]
__device__ __align__(16) __half g_WoT [CDIM * CDIM];        // W_out^T [n][k]
__device__ float  g_embsum[NC * NL * CDIM];                 // cams+level embeds
__device__ __align__(16) __half g_value[(size_t)NC * NH * STOT * DDIM];  // 45.4 MB fp16

// ---------------- fp16 mma helper -------------------------------------------
__device__ __forceinline__ void mma16816(float* c,
    unsigned a0, unsigned a1, unsigned a2, unsigned a3,
    unsigned b0, unsigned b1) {
    asm volatile(
        "mma.sync.aligned.m16n8k16.row.col.f32.f16.f16.f32 "
        "{%0,%1,%2,%3}, {%4,%5,%6,%7}, {%8,%9}, {%0,%1,%2,%3};"
        : "+f"(c[0]), "+f"(c[1]), "+f"(c[2]), "+f"(c[3])
        : "r"(a0), "r"(a1), "r"(a2), "r"(a3), "r"(b0), "r"(b1));
}
__device__ __forceinline__ unsigned pack_h2(float a, float b) {
    __half2 h = __floats2half2_rn(a, b);
    return *(unsigned*)&h;
}

// ---------------- prepA: WhT transpose + embed sums (value's deps only) ------
__global__ __launch_bounds__(256) void k_prepA(
        const float* __restrict__ W_val,
        const float* __restrict__ ce,
        const float* __restrict__ le) {
    int b = blockIdx.x;
    int tid = threadIdx.x;
    if (b < 64) {
        __shared__ float ts[32][33];
        int kt = b / 8, nt = b % 8;
        int w = tid >> 5, lane = tid & 31;
#pragma unroll
        for (int it = 0; it < 4; it++) {
            int r = it * 8 + w;
            ts[r][lane] = W_val[(kt * 32 + r) * 256 + nt * 32 + lane];
        }
        __syncthreads();
#pragma unroll
        for (int it = 0; it < 4; it++) {
            int r = it * 8 + w;
            g_WhT[(nt * 32 + r) * 256 + kt * 32 + lane] = __float2half(ts[lane][r]);
        }
    } else {
        int idx = (b - 64) * 256 + tid;
        if (idx < NC * NL * CDIM) {
            int cl = idx >> 8, c = idx & 255;
            g_embsum[idx] = ce[(cl / 3) * 256 + c] + le[(cl % 3) * 256 + c];
        }
    }
}

// ---------------- prepB: WoaT + WoT transpose + projection -------------------
__global__ __launch_bounds__(256) void k_prepB(
        const float* __restrict__ W_off,
        const float* __restrict__ W_attn,
        const float* __restrict__ W_out,
        const float* __restrict__ cam2ego,
        const float* __restrict__ means,
        const float* __restrict__ intrins,
        const float* __restrict__ post_rots,
        const float* __restrict__ post_trans) {
    int b = blockIdx.x;
    int tid = threadIdx.x;
    if (b < 208) {
        __shared__ float ts[32][33];
        int kt, nt;
        if (b < 144) { kt = b / 18;         nt = b % 18; }
        else         { kt = (b - 144) / 8;  nt = (b - 144) % 8; }
        int w = tid >> 5, lane = tid & 31;
#pragma unroll
        for (int it = 0; it < 4; it++) {
            int r = it * 8 + w;
            int k = kt * 32 + r;
            int n = nt * 32 + lane;
            float v;
            if (b < 144) v = (n < 384) ? W_off[k * 384 + n] : W_attn[k * 192 + (n - 384)];
            else         v = W_out[k * 256 + n];
            ts[r][lane] = v;
        }
        __syncthreads();
#pragma unroll
        for (int it = 0; it < 4; it++) {
            int r = it * 8 + w;
            int n = nt * 32 + r;
            int k = kt * 32 + lane;
            __half hv = __float2half(ts[lane][r]);
            if (b < 144) g_WoaT[n * 256 + k] = hv;
            else         g_WoT [n * 256 + k] = hv;
        }
    } else {
        __shared__ float inv_s[NC * 16];
        if (tid < NC) {
            int c = tid;
            float a[4][8];
            for (int r = 0; r < 4; r++)
                for (int j = 0; j < 4; j++) {
                    a[r][j]     = cam2ego[c * 16 + r * 4 + j];
                    a[r][4 + j] = (r == j) ? 1.f : 0.f;
                }
            for (int col = 0; col < 4; col++) {
                int piv = col; float mxv = fabsf(a[col][col]);
                for (int r = col + 1; r < 4; r++) {
                    float vv = fabsf(a[r][col]);
                    if (vv > mxv) { mxv = vv; piv = r; }
                }
                if (piv != col)
                    for (int j = 0; j < 8; j++) { float t = a[col][j]; a[col][j] = a[piv][j]; a[piv][j] = t; }
                float ivp = 1.f / a[col][col];
                for (int j = 0; j < 8; j++) a[col][j] *= ivp;
                for (int r = 0; r < 4; r++) if (r != col) {
                    float f = a[r][col];
                    for (int j = 0; j < 8; j++) a[r][j] -= f * a[col][j];
                }
            }
            for (int r = 0; r < 4; r++)
                for (int j = 0; j < 4; j++)
                    inv_s[c * 16 + r * 4 + j] = a[r][4 + j];
        }
        __syncthreads();

        int idx = (b - 208) * 256 + tid;     // < 38400
        int cam = idx / NQ, q = idx % NQ;
        float mx = means[q * 3 + 0], my = means[q * 3 + 1], mz = means[q * 3 + 2];
        const float* M = inv_s + cam * 16;
        float X = M[0] * mx + M[1] * my + M[2]  * mz + M[3];
        float Y = M[4] * mx + M[5] * my + M[6]  * mz + M[7];
        float Z = M[8] * mx + M[9] * my + M[10] * mz + M[11];
        const float* I = intrins + cam * 9;
        float u  = I[0] * X + I[1] * Y + I[2] * Z;
        float v  = I[3] * X + I[4] * Y + I[5] * Z;
        float zz = I[6] * X + I[7] * Y + I[8] * Z;
        float iz = 1.f / (zz + 1e-4f);
        float m0 = u * iz, m1 = v * iz, m2 = zz;
        const float* P = post_rots + cam * 9;
        const float* T = post_trans + cam * 3;
        float px = P[0] * m0 + P[1] * m1 + P[2] * m2 + T[0];
        float py = P[3] * m0 + P[4] * m1 + P[5] * m2 + T[1];
        float pz = P[6] * m0 + P[7] * m1 + P[8] * m2 + T[2];
        float cx = px / 1408.0f;
        float cy = py / 512.0f;
        bool msk = (pz > 0.01f) && (cx > 0.f) && (cx < 1.f) && (cy > 0.f) && (cy < 1.f);
        g_coor[idx * 2 + 0] = cx;
        g_coor[idx * 2 + 1] = cy;
        g_mask[idx] = msk ? 1.f : 0.f;
    }
}

// ---------------- value build + GEMM via fp16 mma (bx offset for cam split) --
__global__ __launch_bounds__(256) void k_value(
        const float* __restrict__ feat0,
        const float* __restrict__ feat1,
        const float* __restrict__ feat2,
        const float* __restrict__ b_val, int bxoff) {
    __shared__ __half As[64 * 72];
    __shared__ __half Bs[256 * 72];

    int bx = blockIdx.x + bxoff;
    int cam = bx / 231, rb = bx % 231;
    int lvl, hw, pix0; const float* fb;
    if (rb < 176)      { lvl = 0; hw = 11264; pix0 = rb * 64;          fb = feat0; }
    else if (rb < 220) { lvl = 1; hw = 2816;  pix0 = (rb - 176) * 64;  fb = feat1; }
    else               { lvl = 2; hw = 704;   pix0 = (rb - 220) * 64;  fb = feat2; }
    fb += (size_t)cam * CDIM * hw;
    int m0 = rb * 64;
    const float* emb = g_embsum + (cam * 3 + lvl) * 256;

    int tid = threadIdx.x;
    int w = tid >> 5, lane = tid & 31;
    int g = lane >> 2, tig = lane & 3;

    float acc[4][4][4];
#pragma unroll
    for (int j = 0; j < 4; j++) {
        int d = j * 8 + 2 * tig;
        float bv0 = b_val[w * 32 + d], bv1 = b_val[w * 32 + d + 1];
#pragma unroll
        for (int mi = 0; mi < 4; mi++) {
            acc[mi][j][0] = bv0; acc[mi][j][1] = bv1;
            acc[mi][j][2] = bv0; acc[mi][j][3] = bv1;
        }
    }

    for (int kc = 0; kc < 4; kc++) {
        __syncthreads();
#pragma unroll
        for (int i = 0; i < 4; i++) {
            int cp = w * 4 + i;
            int c = kc * 64 + cp * 2;
            float e0 = emb[c], e1 = emb[c + 1];
#pragma unroll
            for (int j = 0; j < 2; j++) {
                int pix = lane + 32 * j;
                float f0 = fb[(size_t)c * hw + pix0 + pix] + e0;
                float f1 = fb[(size_t)(c + 1) * hw + pix0 + pix] + e1;
                *(unsigned*)&As[pix * 72 + cp * 2] = pack_h2(f0, f1);
            }
        }
#pragma unroll
        for (int t = 0; t < 16; t++) {
            int e = t * 256 + tid;
            int n = e >> 4, seg = e & 15;
            *(unsigned long long*)&Bs[n * 72 + seg * 4] =
                *(const unsigned long long*)&g_WhT[n * 256 + kc * 64 + seg * 4];
        }
        __syncthreads();
#pragma unroll
        for (int ks = 0; ks < 4; ks++) {
            int k2 = ks * 8;
            const unsigned* Ap = (const unsigned*)As;
            const unsigned* Bp = (const unsigned*)Bs;
            unsigned a[4][4];
#pragma unroll
            for (int mi = 0; mi < 4; mi++) {
                int r = mi * 16 + g;
                a[mi][0] = Ap[r * 36 + k2 + tig];
                a[mi][1] = Ap[(r + 8) * 36 + k2 + tig];
                a[mi][2] = Ap[r * 36 + k2 + 4 + tig];
                a[mi][3] = Ap[(r + 8) * 36 + k2 + 4 + tig];
            }
#pragma unroll
            for (int j = 0; j < 4; j++) {
                int n = w * 32 + j * 8 + g;
                unsigned b0 = Bp[n * 36 + k2 + tig];
                unsigned b1 = Bp[n * 36 + k2 + 4 + tig];
#pragma unroll
                for (int mi = 0; mi < 4; mi++)
                    mma16816(acc[mi][j], a[mi][0], a[mi][1], a[mi][2], a[mi][3], b0, b1);
            }
        }
    }
    size_t vbase = ((size_t)(cam * 8 + w) * STOT) * 32;
#pragma unroll
    for (int mi = 0; mi < 4; mi++)
#pragma unroll
        for (int j = 0; j < 4; j++) {
            int d = j * 8 + 2 * tig;
            int s = m0 + mi * 16 + g;
            *(unsigned*)&g_value[vbase + (size_t)s * 32 + d] = pack_h2(acc[mi][j][0], acc[mi][j][1]);
            *(unsigned*)&g_value[vbase + (size_t)(s + 8) * 32 + d] = pack_h2(acc[mi][j][2], acc[mi][j][3]);
        }
}

// ---------------- offsets+attn GEMM via fp16 mma, softmax fused --------------
__global__ __launch_bounds__(256) void k_offattn(
        const float* __restrict__ feature,
        const float* __restrict__ b_off, const float* __restrict__ b_attn) {
    __shared__ __half As[64 * 72];
    __shared__ __half Bs[192 * 72];

    int q0 = blockIdx.x * 64;
    int ny = blockIdx.y;           // 0..2
    int tid = threadIdx.x;
    int w = tid >> 5, lane = tid & 31;
    int g = lane >> 2, tig = lane & 3;

    float acc[4][3][4];
#pragma unroll
    for (int j = 0; j < 3; j++) {
        int col = ny * 192 + w * 24 + j * 8 + 2 * tig;
        float bv0 = (col < 384) ? b_off[col] : b_attn[col - 384];
        float bv1 = (col + 1 < 384) ? b_off[col + 1] : b_attn[col + 1 - 384];
#pragma unroll
        for (int mi = 0; mi < 4; mi++) {
            acc[mi][j][0] = bv0; acc[mi][j][1] = bv1;
            acc[mi][j][2] = bv0; acc[mi][j][3] = bv1;
        }
    }

    for (int kc = 0; kc < 4; kc++) {
        __syncthreads();
#pragma unroll
        for (int i = 0; i < 8; i++) {
            int row = w * 8 + i;
            const float2 f = *(const float2*)&feature[(q0 + row) * 256 + kc * 64 + 2 * lane];
            *(unsigned*)&As[row * 72 + 2 * lane] = pack_h2(f.x, f.y);
        }
#pragma unroll
        for (int t = 0; t < 12; t++) {
            int e = t * 256 + tid;
            int n = e >> 4, seg = e & 15;
            *(unsigned long long*)&Bs[n * 72 + seg * 4] =
                *(const unsigned long long*)&g_WoaT[(ny * 192 + n) * 256 + kc * 64 + seg * 4];
        }
        __syncthreads();
#pragma unroll
        for (int ks = 0; ks < 4; ks++) {
            int k2 = ks * 8;
            const unsigned* Ap = (const unsigned*)As;
            const unsigned* Bp = (const unsigned*)Bs;
            unsigned a[4][4];
#pragma unroll
            for (int mi = 0; mi < 4; mi++) {
                int r = mi * 16 + g;
                a[mi][0] = Ap[r * 36 + k2 + tig];
                a[mi][1] = Ap[(r + 8) * 36 + k2 + tig];
                a[mi][2] = Ap[r * 36 + k2 + 4 + tig];
                a[mi][3] = Ap[(r + 8) * 36 + k2 + 4 + tig];
            }
#pragma unroll
            for (int j = 0; j < 3; j++) {
                int n = w * 24 + j * 8 + g;
                unsigned b0 = Bp[n * 36 + k2 + tig];
                unsigned b1 = Bp[n * 36 + k2 + 4 + tig];
#pragma unroll
                for (int mi = 0; mi < 4; mi++)
                    mma16816(acc[mi][j], a[mi][0], a[mi][1], a[mi][2], a[mi][3], b0, b1);
            }
        }
    }

    if (ny < 2) {
#pragma unroll
        for (int mi = 0; mi < 4; mi++)
#pragma unroll
            for (int j = 0; j < 3; j++) {
                int col = ny * 192 + w * 24 + j * 8 + 2 * tig;
                int q = q0 + mi * 16 + g;
                *(float2*)&g_off[q * 384 + col] = make_float2(acc[mi][j][0], acc[mi][j][1]);
                *(float2*)&g_off[(q + 8) * 384 + col] = make_float2(acc[mi][j][2], acc[mi][j][3]);
            }
    } else {
        const unsigned FULL = 0xFFFFFFFFu;
#pragma unroll
        for (int mi = 0; mi < 4; mi++) {
            float mA = -1e30f, mB = -1e30f;
#pragma unroll
            for (int j = 0; j < 3; j++) {
                mA = fmaxf(mA, fmaxf(acc[mi][j][0], acc[mi][j][1]));
                mB = fmaxf(mB, fmaxf(acc[mi][j][2], acc[mi][j][3]));
            }
            mA = fmaxf(mA, __shfl_xor_sync(FULL, mA, 1));
            mA = fmaxf(mA, __shfl_xor_sync(FULL, mA, 2));
            mB = fmaxf(mB, __shfl_xor_sync(FULL, mB, 1));
            mB = fmaxf(mB, __shfl_xor_sync(FULL, mB, 2));
            float sA = 0.f, sB = 0.f;
#pragma unroll
            for (int j = 0; j < 3; j++) {
                acc[mi][j][0] = __expf(acc[mi][j][0] - mA);
                acc[mi][j][1] = __expf(acc[mi][j][1] - mA);
                acc[mi][j][2] = __expf(acc[mi][j][2] - mB);
                acc[mi][j][3] = __expf(acc[mi][j][3] - mB);
                sA += acc[mi][j][0] + acc[mi][j][1];
                sB += acc[mi][j][2] + acc[mi][j][3];
            }
            sA += __shfl_xor_sync(FULL, sA, 1);
            sA += __shfl_xor_sync(FULL, sA, 2);
            sB += __shfl_xor_sync(FULL, sB, 1);
            sB += __shfl_xor_sync(FULL, sB, 2);
            float iA = 1.f / sA, iB = 1.f / sB;
#pragma unroll
            for (int j = 0; j < 3; j++) {
                int col = w * 24 + j * 8 + 2 * tig;
                int q = q0 + mi * 16 + g;
                *(float2*)&g_attn[q * 192 + col] =
                    make_float2(acc[mi][j][0] * iA, acc[mi][j][1] * iA);
                *(float2*)&g_attn[(q + 8) * 192 + col] =
                    make_float2(acc[mi][j][2] * iB, acc[mi][j][3] * iB);
            }
        }
    }
}

// ---------------- half-gather: cams [cam0, cam0+3), optional accumulate ------
// Descs: uint2 per (tap,row) = {byte_off, h2(wlo,whi)}; 72 taps/head.
// 2 taps per warp-iteration; fp32 flush every 12 taps (6 groups x 6 iters).
__global__ __launch_bounds__(256) void k_gather(int cam0, int accum) {
    __shared__ __align__(16) uint2 s_desc[1152];
    __shared__ float s_off[384];
    __shared__ float s_attn[192];
    __shared__ float s_coor[12];
    __shared__ float s_mask[6];

    int q = blockIdx.x, tid = threadIdx.x;

    s_off[tid] = g_off[q * 384 + tid];
    if (tid < 128) s_off[256 + tid] = g_off[q * 384 + 256 + tid];
    if (tid < 192) s_attn[tid] = g_attn[q * 192 + tid];
    if (tid < 12)  s_coor[tid] = g_coor[((tid >> 1) * NQ + q) * 2 + (tid & 1)];
    if (tid < 6)   s_mask[tid] = g_mask[tid * NQ + q];
    __syncthreads();

    int h = tid >> 5, lane = tid & 31;

    float cnt = s_mask[0] + s_mask[1] + s_mask[2] + s_mask[3] + s_mask[4] + s_mask[5];
    float inv = 1.f / fmaxf(cnt, 1.f);

    const int lw[3]  = {176, 88, 44};
    const int lhh[3] = {64, 32, 16};
    const int lst[3] = {0, 11264, 14080};

    // descriptors for this head, cams cam0..cam0+2 (72 taps)
    for (int i = lane; i < 72; i += 32) {
        int cam = cam0 + i / 24, l = (i >> 3) % 3, p = i & 7;
        int w = lw[l], hh = lhh[l];
        float cx = s_coor[cam * 2], cy = s_coor[cam * 2 + 1];
        int oi = ((h * 3 + l) * 8 + p) * 2;
        float x = cx * (float)w  - 0.5f + s_off[oi];
        float y = cy * (float)hh - 0.5f + s_off[oi + 1];
        float am = s_attn[h * 24 + l * 8 + p] * s_mask[cam] * inv;

        float xf = floorf(x), yf = floorf(y);
        float tx = x - xf, ty = y - yf;
        int x0 = (int)xf, y0 = (int)yf;
        float wx0 = ((x0 >= 0) && (x0 < w)) ? (1.f - tx) : 0.f;
        float wx1 = ((x0 + 1 >= 0) && (x0 + 1 < w)) ? tx : 0.f;
        int xb = min(max(x0, 0), w - 2);
        float wlo = (xb == x0) ? wx0 : ((xb == x0 + 1) ? wx1 : 0.f);
        float whi = (xb == x0) ? wx1 : ((xb == x0 - 1) ? wx0 : 0.f);

        unsigned base = (unsigned)((cam * 8 + h) * STOT + lst[l] + xb);
        {
            int r = y0;
            float wy = ((r >= 0) && (r < hh)) ? (1.f - ty) : 0.f;
            int rr = min(max(r, 0), hh - 1);
            uint2 d;
            d.x = (base + (unsigned)(rr * w)) * 64u;
            d.y = pack_h2(am * wy * wlo, am * wy * whi);
            s_desc[(h * 72 + i) * 2 + 0] = d;
        }
        {
            int r = y0 + 1;
            float wy = ((r >= 0) && (r < hh)) ? ty : 0.f;
            int rr = min(max(r, 0), hh - 1);
            uint2 d;
            d.x = (base + (unsigned)(rr * w)) * 64u;
            d.y = pack_h2(am * wy * wlo, am * wy * whi);
            s_desc[(h * 72 + i) * 2 + 1] = d;
        }
    }
    __syncwarp();

    int t16 = lane >> 4;            // tap parity
    int r8  = (lane >> 3) & 1;      // row
    int lc  = lane & 7;             // 16B segment (8 channels)
    unsigned laneconst = (unsigned)(lc * 16);
    unsigned wsel = (lc >= 4) ? 0x3232u : 0x1010u;
    const uint2* dp = s_desc + h * 144 + 2 * t16 + r8;
    const char* vb = (const char*)g_value;

    float a0 = 0.f, a1 = 0.f, a2 = 0.f, a3 = 0.f;
    float a4 = 0.f, a5 = 0.f, a6 = 0.f, a7 = 0.f;
#pragma unroll 1
    for (int grp = 0; grp < 6; grp++) {
        __half2 h0 = __floats2half2_rn(0.f, 0.f);
        __half2 h1 = h0, h2 = h0, h3 = h0;
#pragma unroll
        for (int k = 0; k < 6; k++) {
            uint2 d = dp[(grp * 6 + k) * 4];
            unsigned wp;
            asm("prmt.b32 %0, %1, %1, %2;" : "=r"(wp) : "r"(d.y), "r"(wsel));
            uint4 v = *(const uint4*)(vb + d.x + laneconst);
            h0 = __hfma2(*(__half2*)&v.x, *(__half2*)&wp, h0);
            h1 = __hfma2(*(__half2*)&v.y, *(__half2*)&wp, h1);
            h2 = __hfma2(*(__half2*)&v.z, *(__half2*)&wp, h2);
            h3 = __hfma2(*(__half2*)&v.w, *(__half2*)&wp, h3);
        }
        float2 f0 = __half22float2(h0);
        float2 f1 = __half22float2(h1);
        float2 f2 = __half22float2(h2);
        float2 f3 = __half22float2(h3);
        a0 += f0.x; a1 += f0.y; a2 += f1.x; a3 += f1.y;
        a4 += f2.x; a5 += f2.y; a6 += f3.x; a7 += f3.y;
    }

    const unsigned FULL = 0xFFFFFFFFu;
#pragma unroll
    for (int o = 4; o <= 16; o <<= 1) {
        a0 += __shfl_xor_sync(FULL, a0, o);
        a1 += __shfl_xor_sync(FULL, a1, o);
        a2 += __shfl_xor_sync(FULL, a2, o);
        a3 += __shfl_xor_sync(FULL, a3, o);
        a4 += __shfl_xor_sync(FULL, a4, o);
        a5 += __shfl_xor_sync(FULL, a5, o);
        a6 += __shfl_xor_sync(FULL, a6, o);
        a7 += __shfl_xor_sync(FULL, a7, o);
    }

    if (lane < 4) {
        float* sp = &g_slots[q * 256 + h * 32 + lane * 8];
        if (accum) {
            float4 p0 = *(float4*)sp;
            float4 p1 = *(float4*)(sp + 4);
            a0 += p0.x; a1 += p0.y; a2 += p0.z; a3 += p0.w;
            a4 += p1.x; a5 += p1.y; a6 += p1.z; a7 += p1.w;
        }
        *(float4*)sp       = make_float4(a0, a1, a2, a3);
        *(float4*)(sp + 4) = make_float4(a4, a5, a6, a7);
    }
}

// ---------------- out projection via fp16 mma + residual + LayerNorm ---------
__global__ __launch_bounds__(256) void k_outln(
        const float* __restrict__ feature,
        const float* __restrict__ b_out,
        const float* __restrict__ ln_g, const float* __restrict__ ln_b,
        float* __restrict__ out) {
    __shared__ __half As[64 * 72];
    __shared__ __half Bs[256 * 72];
    __shared__ float red_s[64 * 8];
    __shared__ float red2_s[64 * 8];

    int q0 = blockIdx.x * 64;
    int tid = threadIdx.x;
    int w = tid >> 5, lane = tid & 31;
    int g = lane >> 2, tig = lane & 3;

    float acc[4][4][4];
#pragma unroll
    for (int j = 0; j < 4; j++) {
        int col = w * 32 + j * 8 + 2 * tig;
        float bv0 = b_out[col], bv1 = b_out[col + 1];
#pragma unroll
        for (int mi = 0; mi < 4; mi++) {
            acc[mi][j][0] = bv0; acc[mi][j][1] = bv1;
            acc[mi][j][2] = bv0; acc[mi][j][3] = bv1;
        }
    }

    for (int kc = 0; kc < 4; kc++) {
        __syncthreads();
#pragma unroll
        for (int i = 0; i < 8; i++) {
            int row = w * 8 + i;
            const float2 f = *(const float2*)&g_slots[(q0 + row) * 256 + kc * 64 + 2 * lane];
            *(unsigned*)&As[row * 72 + 2 * lane] = pack_h2(f.x, f.y);
        }
#pragma unroll
        for (int t = 0; t < 16; t++) {
            int e = t * 256 + tid;
            int n = e >> 4, seg = e & 15;
            *(unsigned long long*)&Bs[n * 72 + seg * 4] =
                *(const unsigned long long*)&g_WoT[n * 256 + kc * 64 + seg * 4];
        }
        __syncthreads();
#pragma unroll
        for (int ks = 0; ks < 4; ks++) {
            int k2 = ks * 8;
            const unsigned* Ap = (const unsigned*)As;
            const unsigned* Bp = (const unsigned*)Bs;
            unsigned a[4][4];
#pragma unroll
            for (int mi = 0; mi < 4; mi++) {
                int r = mi * 16 + g;
                a[mi][0] = Ap[r * 36 + k2 + tig];
                a[mi][1] = Ap[(r + 8) * 36 + k2 + tig];
                a[mi][2] = Ap[r * 36 + k2 + 4 + tig];
                a[mi][3] = Ap[(r + 8) * 36 + k2 + 4 + tig];
            }
#pragma unroll
            for (int j = 0; j < 4; j++) {
                int n = w * 32 + j * 8 + g;
                unsigned b0 = Bp[n * 36 + k2 + tig];
                unsigned b1 = Bp[n * 36 + k2 + 4 + tig];
#pragma unroll
                for (int mi = 0; mi < 4; mi++)
                    mma16816(acc[mi][j], a[mi][0], a[mi][1], a[mi][2], a[mi][3], b0, b1);
            }
        }
    }

    const unsigned FULL = 0xFFFFFFFFu;
#pragma unroll
    for (int mi = 0; mi < 4; mi++) {
        float s0 = 0.f, s1 = 0.f, ss0 = 0.f, ss1 = 0.f;
#pragma unroll
        for (int j = 0; j < 4; j++) {
            int col = w * 32 + j * 8 + 2 * tig;
            int q = q0 + mi * 16 + g;
            float2 fA = *(const float2*)&feature[q * 256 + col];
            float2 fB = *(const float2*)&feature[(q + 8) * 256 + col];
            acc[mi][j][0] += fA.x; acc[mi][j][1] += fA.y;
            acc[mi][j][2] += fB.x; acc[mi][j][3] += fB.y;
            s0  += acc[mi][j][0] + acc[mi][j][1];
            s1  += acc[mi][j][2] + acc[mi][j][3];
            ss0 += acc[mi][j][0] * acc[mi][j][0] + acc[mi][j][1] * acc[mi][j][1];
            ss1 += acc[mi][j][2] * acc[mi][j][2] + acc[mi][j][3] * acc[mi][j][3];
        }
        s0  += __shfl_xor_sync(FULL, s0, 1);  s0  += __shfl_xor_sync(FULL, s0, 2);
        s1  += __shfl_xor_sync(FULL, s1, 1);  s1  += __shfl_xor_sync(FULL, s1, 2);
        ss0 += __shfl_xor_sync(FULL, ss0, 1); ss0 += __shfl_xor_sync(FULL, ss0, 2);
        ss1 += __shfl_xor_sync(FULL, ss1, 1); ss1 += __shfl_xor_sync(FULL, ss1, 2);
        if (tig == 0) {
            red_s [(mi * 16 + g) * 8 + w] = s0;
            red_s [(mi * 16 + 8 + g) * 8 + w] = s1;
            red2_s[(mi * 16 + g) * 8 + w] = ss0;
            red2_s[(mi * 16 + 8 + g) * 8 + w] = ss1;
        }
    }
    __syncthreads();

#pragma unroll
    for (int mi = 0; mi < 4; mi++) {
        float sum0 = 0.f, sum1 = 0.f, sq0 = 0.f, sq1 = 0.f;
#pragma unroll
        for (int ww = 0; ww < 8; ww++) {
            sum0 += red_s [(mi * 16 + g) * 8 + ww];
            sum1 += red_s [(mi * 16 + 8 + g) * 8 + ww];
            sq0  += red2_s[(mi * 16 + g) * 8 + ww];
            sq1  += red2_s[(mi * 16 + 8 + g) * 8 + ww];
        }
        float mu0 = sum0 * (1.f / 256.f), mu1 = sum1 * (1.f / 256.f);
        float rv0 = rsqrtf(sq0 * (1.f / 256.f) - mu0 * mu0 + 1e-5f);
        float rv1 = rsqrtf(sq1 * (1.f / 256.f) - mu1 * mu1 + 1e-5f);
#pragma unroll
        for (int j = 0; j < 4; j++) {
            int col = w * 32 + j * 8 + 2 * tig;
            int q = q0 + mi * 16 + g;
            float2 gg = *(const float2*)&ln_g[col];
            float2 bb = *(const float2*)&ln_b[col];
            *(float2*)&out[q * 256 + col] = make_float2(
                (acc[mi][j][0] - mu0) * rv0 * gg.x + bb.x,
                (acc[mi][j][1] - mu0) * rv0 * gg.y + bb.y);
            *(float2*)&out[(q + 8) * 256 + col] = make_float2(
                (acc[mi][j][2] - mu1) * rv1 * gg.x + bb.x,
                (acc[mi][j][3] - mu1) * rv1 * gg.y + bb.y);
        }
    }
}

// ---------------- launch: pipelined cam-split value/gather -------------------
extern "C" void kernel_launch(void* const* d_in, const int* in_sizes, int n_in,
                              void* d_out, int out_size) {
    const float* means      = (const float*)d_in[0];
    const float* feature    = (const float*)d_in[1];
    const float* feat0      = (const float*)d_in[2];
    const float* feat1      = (const float*)d_in[3];
    const float* feat2      = (const float*)d_in[4];
    const float* cam2ego    = (const float*)d_in[5];
    const float* intrins    = (const float*)d_in[6];
    const float* post_rots  = (const float*)d_in[7];
    const float* post_trans = (const float*)d_in[8];
    const float* W_off      = (const float*)d_in[9];
    const float* b_off      = (const float*)d_in[10];
    const float* W_attn     = (const float*)d_in[11];
    const float* b_attn     = (const float*)d_in[12];
    const float* W_val      = (const float*)d_in[13];
    const float* b_val      = (const float*)d_in[14];
    const float* W_out      = (const float*)d_in[15];
    const float* b_out      = (const float*)d_in[16];
    const float* ce         = (const float*)d_in[17];
    const float* le         = (const float*)d_in[18];
    const float* ln_g       = (const float*)d_in[19];
    const float* ln_b       = (const float*)d_in[20];
    float* out = (float*)d_out;

    cudaStream_t s1;
    cudaEvent_t eFork, eA, eB;
    cudaStreamCreateWithFlags(&s1, cudaStreamNonBlocking);
    cudaEventCreateWithFlags(&eFork, cudaEventDisableTiming);
    cudaEventCreateWithFlags(&eA,    cudaEventDisableTiming);
    cudaEventCreateWithFlags(&eB,    cudaEventDisableTiming);

    // fork: s1 runs prepA -> value(cams 0-2) -> value(cams 3-5)
    cudaEventRecord(eFork, 0);
    cudaStreamWaitEvent(s1, eFork, 0);

    k_prepA<<<82, 256, 0, s1>>>(W_val, ce, le);
    k_value<<<693, 256, 0, s1>>>(feat0, feat1, feat2, b_val, 0);
    cudaEventRecord(eA, s1);
    k_value<<<693, 256, 0, s1>>>(feat0, feat1, feat2, b_val, 693);
    cudaEventRecord(eB, s1);

    // main: prepB -> offattn -> gather(cams 0-2) -> gather(cams 3-5, accum) -> outln
    k_prepB<<<358, 256>>>(W_off, W_attn, W_out, cam2ego, means,
                          intrins, post_rots, post_trans);
    k_offattn<<<dim3(100, 3), 256>>>(feature, b_off, b_attn);

    cudaStreamWaitEvent(0, eA, 0);
    k_gather<<<NQ, 256>>>(0, 0);
    cudaStreamWaitEvent(0, eB, 0);
    k_gather<<<NQ, 256>>>(3, 1);
    k_outln<<<100, 256>>>(feature, b_out, ln_g, ln_b, out);
}

// round 15
// speedup vs baseline: 1.0739x; 1.0739x over previous
#include <cuda_runtime.h>
#include <cuda_fp16.h>
#include <math.h>

#define NC   6
#define NH   8
#define NL   3
#define NPT  8
#define CDIM 256
#define DDIM 32
#define NQ   6400
#define STOT 14784   // 64*176 + 32*88 + 16*44

// ---------------- scratch (device globals; no allocations allowed) ----------
__device__ float  g_coor[NC * NQ * 2];
__device__ float  g_mask[NC * NQ];
__device__ float  g_off [NQ * 384];
__device__ float  g_attn[NQ * 192];
__device__ float  g_slots[NQ * CDIM];
__device__ __align__(16) __half g_WhT [CDIM * CDIM];        // W_val^T [n][k]
__device__ __align__(16) __half g_WoaT[576 * CDIM];         // [W_off|W_attn]^T [n][k]
__device__ __align__(16) __half g_WoT [CDIM * CDIM];        // W_out^T [n][k]
__device__ float  g_embsum[NC * NL * CDIM];                 // cams+level embeds
__device__ __align__(16) __half g_value[(size_t)NC * NH * STOT * DDIM];  // 45.4 MB fp16

// ---------------- fp16 mma helper -------------------------------------------
__device__ __forceinline__ void mma16816(float* c,
    unsigned a0, unsigned a1, unsigned a2, unsigned a3,
    unsigned b0, unsigned b1) {
    asm volatile(
        "mma.sync.aligned.m16n8k16.row.col.f32.f16.f16.f32 "
        "{%0,%1,%2,%3}, {%4,%5,%6,%7}, {%8,%9}, {%0,%1,%2,%3};"
        : "+f"(c[0]), "+f"(c[1]), "+f"(c[2]), "+f"(c[3])
        : "r"(a0), "r"(a1), "r"(a2), "r"(a3), "r"(b0), "r"(b1));
}
__device__ __forceinline__ unsigned pack_h2(float a, float b) {
    __half2 h = __floats2half2_rn(a, b);
    return *(unsigned*)&h;
}

// ---------------- prep+projinv: one kernel, block-range dispatch --------------
__global__ __launch_bounds__(256) void k_prep(
        const float* __restrict__ W_val,
        const float* __restrict__ W_off,
        const float* __restrict__ W_attn,
        const float* __restrict__ W_out,
        const float* __restrict__ ce,
        const float* __restrict__ le,
        const float* __restrict__ cam2ego,
        const float* __restrict__ means,
        const float* __restrict__ intrins,
        const float* __restrict__ post_rots,
        const float* __restrict__ post_trans) {
    int b = blockIdx.x;
    int tid = threadIdx.x;
    if (b < 272) {
        __shared__ float ts[32][33];
        int kt, nt;
        if (b < 64)       { kt = b / 8;         nt = b % 8; }
        else if (b < 208) { kt = (b - 64) / 18; nt = (b - 64) % 18; }
        else              { kt = (b - 208) / 8; nt = (b - 208) % 8; }
        int w = tid >> 5, lane = tid & 31;
#pragma unroll
        for (int it = 0; it < 4; it++) {
            int r = it * 8 + w;
            int k = kt * 32 + r;
            int n = nt * 32 + lane;
            float v;
            if (b < 64)       v = W_val[k * 256 + n];
            else if (b < 208) v = (n < 384) ? W_off[k * 384 + n] : W_attn[k * 192 + (n - 384)];
            else              v = W_out[k * 256 + n];
            ts[r][lane] = v;
        }
        __syncthreads();
#pragma unroll
        for (int it = 0; it < 4; it++) {
            int r = it * 8 + w;
            int n = nt * 32 + r;
            int k = kt * 32 + lane;
            __half hv = __float2half(ts[lane][r]);
            if (b < 64)       g_WhT [n * 256 + k] = hv;
            else if (b < 208) g_WoaT[n * 256 + k] = hv;
            else              g_WoT [n * 256 + k] = hv;
        }
    } else if (b < 290) {
        int idx = (b - 272) * 256 + tid;
        if (idx < NC * NL * CDIM) {
            int cl = idx >> 8, c = idx & 255;
            g_embsum[idx] = ce[(cl / 3) * 256 + c] + le[(cl % 3) * 256 + c];
        }
    } else {
        __shared__ float inv_s[NC * 16];
        if (tid < NC) {
            int c = tid;
            float a[4][8];
            for (int r = 0; r < 4; r++)
                for (int j = 0; j < 4; j++) {
                    a[r][j]     = cam2ego[c * 16 + r * 4 + j];
                    a[r][4 + j] = (r == j) ? 1.f : 0.f;
                }
            for (int col = 0; col < 4; col++) {
                int piv = col; float mxv = fabsf(a[col][col]);
                for (int r = col + 1; r < 4; r++) {
                    float vv = fabsf(a[r][col]);
                    if (vv > mxv) { mxv = vv; piv = r; }
                }
                if (piv != col)
                    for (int j = 0; j < 8; j++) { float t = a[col][j]; a[col][j] = a[piv][j]; a[piv][j] = t; }
                float ivp = 1.f / a[col][col];
                for (int j = 0; j < 8; j++) a[col][j] *= ivp;
                for (int r = 0; r < 4; r++) if (r != col) {
                    float f = a[r][col];
                    for (int j = 0; j < 8; j++) a[r][j] -= f * a[col][j];
                }
            }
            for (int r = 0; r < 4; r++)
                for (int j = 0; j < 4; j++)
                    inv_s[c * 16 + r * 4 + j] = a[r][4 + j];
        }
        __syncthreads();

        int idx = (b - 290) * 256 + tid;     // < 38400
        int cam = idx / NQ, q = idx % NQ;
        float mx = means[q * 3 + 0], my = means[q * 3 + 1], mz = means[q * 3 + 2];
        const float* M = inv_s + cam * 16;
        float X = M[0] * mx + M[1] * my + M[2]  * mz + M[3];
        float Y = M[4] * mx + M[5] * my + M[6]  * mz + M[7];
        float Z = M[8] * mx + M[9] * my + M[10] * mz + M[11];
        const float* I = intrins + cam * 9;
        float u  = I[0] * X + I[1] * Y + I[2] * Z;
        float v  = I[3] * X + I[4] * Y + I[5] * Z;
        float zz = I[6] * X + I[7] * Y + I[8] * Z;
        float iz = 1.f / (zz + 1e-4f);
        float m0 = u * iz, m1 = v * iz, m2 = zz;
        const float* P = post_rots + cam * 9;
        const float* T = post_trans + cam * 3;
        float px = P[0] * m0 + P[1] * m1 + P[2] * m2 + T[0];
        float py = P[3] * m0 + P[4] * m1 + P[5] * m2 + T[1];
        float pz = P[6] * m0 + P[7] * m1 + P[8] * m2 + T[2];
        float cx = px / 1408.0f;
        float cy = py / 512.0f;
        bool msk = (pz > 0.01f) && (cx > 0.f) && (cx < 1.f) && (cy > 0.f) && (cy < 1.f);
        g_coor[idx * 2 + 0] = cx;
        g_coor[idx * 2 + 1] = cy;
        g_mask[idx] = msk ? 1.f : 0.f;
    }
}

// ---------------- value build + GEMM via fp16 mma ----------------------------
__global__ __launch_bounds__(256) void k_value(
        const float* __restrict__ feat0,
        const float* __restrict__ feat1,
        const float* __restrict__ feat2,
        const float* __restrict__ b_val) {
    __shared__ __half As[64 * 72];
    __shared__ __half Bs[256 * 72];

    int bx = blockIdx.x;
    int cam = bx / 231, rb = bx % 231;
    int lvl, hw, pix0; const float* fb;
    if (rb < 176)      { lvl = 0; hw = 11264; pix0 = rb * 64;          fb = feat0; }
    else if (rb < 220) { lvl = 1; hw = 2816;  pix0 = (rb - 176) * 64;  fb = feat1; }
    else               { lvl = 2; hw = 704;   pix0 = (rb - 220) * 64;  fb = feat2; }
    fb += (size_t)cam * CDIM * hw;
    int m0 = rb * 64;
    const float* emb = g_embsum + (cam * 3 + lvl) * 256;

    int tid = threadIdx.x;
    int w = tid >> 5, lane = tid & 31;
    int g = lane >> 2, tig = lane & 3;

    float acc[4][4][4];
#pragma unroll
    for (int j = 0; j < 4; j++) {
        int d = j * 8 + 2 * tig;
        float bv0 = b_val[w * 32 + d], bv1 = b_val[w * 32 + d + 1];
#pragma unroll
        for (int mi = 0; mi < 4; mi++) {
            acc[mi][j][0] = bv0; acc[mi][j][1] = bv1;
            acc[mi][j][2] = bv0; acc[mi][j][3] = bv1;
        }
    }

    for (int kc = 0; kc < 4; kc++) {
        __syncthreads();
#pragma unroll
        for (int i = 0; i < 4; i++) {
            int cp = w * 4 + i;
            int c = kc * 64 + cp * 2;
            float e0 = emb[c], e1 = emb[c + 1];
#pragma unroll
            for (int j = 0; j < 2; j++) {
                int pix = lane + 32 * j;
                float f0 = fb[(size_t)c * hw + pix0 + pix] + e0;
                float f1 = fb[(size_t)(c + 1) * hw + pix0 + pix] + e1;
                *(unsigned*)&As[pix * 72 + cp * 2] = pack_h2(f0, f1);
            }
        }
#pragma unroll
        for (int t = 0; t < 16; t++) {
            int e = t * 256 + tid;
            int n = e >> 4, seg = e & 15;
            *(unsigned long long*)&Bs[n * 72 + seg * 4] =
                *(const unsigned long long*)&g_WhT[n * 256 + kc * 64 + seg * 4];
        }
        __syncthreads();
#pragma unroll
        for (int ks = 0; ks < 4; ks++) {
            int k2 = ks * 8;
            const unsigned* Ap = (const unsigned*)As;
            const unsigned* Bp = (const unsigned*)Bs;
            unsigned a[4][4];
#pragma unroll
            for (int mi = 0; mi < 4; mi++) {
                int r = mi * 16 + g;
                a[mi][0] = Ap[r * 36 + k2 + tig];
                a[mi][1] = Ap[(r + 8) * 36 + k2 + tig];
                a[mi][2] = Ap[r * 36 + k2 + 4 + tig];
                a[mi][3] = Ap[(r + 8) * 36 + k2 + 4 + tig];
            }
#pragma unroll
            for (int j = 0; j < 4; j++) {
                int n = w * 32 + j * 8 + g;
                unsigned b0 = Bp[n * 36 + k2 + tig];
                unsigned b1 = Bp[n * 36 + k2 + 4 + tig];
#pragma unroll
                for (int mi = 0; mi < 4; mi++)
                    mma16816(acc[mi][j], a[mi][0], a[mi][1], a[mi][2], a[mi][3], b0, b1);
            }
        }
    }
    size_t vbase = ((size_t)(cam * 8 + w) * STOT) * 32;
#pragma unroll
    for (int mi = 0; mi < 4; mi++)
#pragma unroll
        for (int j = 0; j < 4; j++) {
            int d = j * 8 + 2 * tig;
            int s = m0 + mi * 16 + g;
            *(unsigned*)&g_value[vbase + (size_t)s * 32 + d] = pack_h2(acc[mi][j][0], acc[mi][j][1]);
            *(unsigned*)&g_value[vbase + (size_t)(s + 8) * 32 + d] = pack_h2(acc[mi][j][2], acc[mi][j][3]);
        }
}

// ---------------- offsets+attn GEMM via fp16 mma, softmax fused --------------
__global__ __launch_bounds__(256) void k_offattn(
        const float* __restrict__ feature,
        const float* __restrict__ b_off, const float* __restrict__ b_attn) {
    __shared__ __half As[64 * 72];
    __shared__ __half Bs[192 * 72];

    int q0 = blockIdx.x * 64;
    int ny = blockIdx.y;           // 0..2
    int tid = threadIdx.x;
    int w = tid >> 5, lane = tid & 31;
    int g = lane >> 2, tig = lane & 3;

    float acc[4][3][4];
#pragma unroll
    for (int j = 0; j < 3; j++) {
        int col = ny * 192 + w * 24 + j * 8 + 2 * tig;
        float bv0 = (col < 384) ? b_off[col] : b_attn[col - 384];
        float bv1 = (col + 1 < 384) ? b_off[col + 1] : b_attn[col + 1 - 384];
#pragma unroll
        for (int mi = 0; mi < 4; mi++) {
            acc[mi][j][0] = bv0; acc[mi][j][1] = bv1;
            acc[mi][j][2] = bv0; acc[mi][j][3] = bv1;
        }
    }

    for (int kc = 0; kc < 4; kc++) {
        __syncthreads();
#pragma unroll
        for (int i = 0; i < 8; i++) {
            int row = w * 8 + i;
            const float2 f = *(const float2*)&feature[(q0 + row) * 256 + kc * 64 + 2 * lane];
            *(unsigned*)&As[row * 72 + 2 * lane] = pack_h2(f.x, f.y);
        }
#pragma unroll
        for (int t = 0; t < 12; t++) {
            int e = t * 256 + tid;
            int n = e >> 4, seg = e & 15;
            *(unsigned long long*)&Bs[n * 72 + seg * 4] =
                *(const unsigned long long*)&g_WoaT[(ny * 192 + n) * 256 + kc * 64 + seg * 4];
        }
        __syncthreads();
#pragma unroll
        for (int ks = 0; ks < 4; ks++) {
            int k2 = ks * 8;
            const unsigned* Ap = (const unsigned*)As;
            const unsigned* Bp = (const unsigned*)Bs;
            unsigned a[4][4];
#pragma unroll
            for (int mi = 0; mi < 4; mi++) {
                int r = mi * 16 + g;
                a[mi][0] = Ap[r * 36 + k2 + tig];
                a[mi][1] = Ap[(r + 8) * 36 + k2 + tig];
                a[mi][2] = Ap[r * 36 + k2 + 4 + tig];
                a[mi][3] = Ap[(r + 8) * 36 + k2 + 4 + tig];
            }
#pragma unroll
            for (int j = 0; j < 3; j++) {
                int n = w * 24 + j * 8 + g;
                unsigned b0 = Bp[n * 36 + k2 + tig];
                unsigned b1 = Bp[n * 36 + k2 + 4 + tig];
#pragma unroll
                for (int mi = 0; mi < 4; mi++)
                    mma16816(acc[mi][j], a[mi][0], a[mi][1], a[mi][2], a[mi][3], b0, b1);
            }
        }
    }

    if (ny < 2) {
#pragma unroll
        for (int mi = 0; mi < 4; mi++)
#pragma unroll
            for (int j = 0; j < 3; j++) {
                int col = ny * 192 + w * 24 + j * 8 + 2 * tig;
                int q = q0 + mi * 16 + g;
                *(float2*)&g_off[q * 384 + col] = make_float2(acc[mi][j][0], acc[mi][j][1]);
                *(float2*)&g_off[(q + 8) * 384 + col] = make_float2(acc[mi][j][2], acc[mi][j][3]);
            }
    } else {
        const unsigned FULL = 0xFFFFFFFFu;
#pragma unroll
        for (int mi = 0; mi < 4; mi++) {
            float mA = -1e30f, mB = -1e30f;
#pragma unroll
            for (int j = 0; j < 3; j++) {
                mA = fmaxf(mA, fmaxf(acc[mi][j][0], acc[mi][j][1]));
                mB = fmaxf(mB, fmaxf(acc[mi][j][2], acc[mi][j][3]));
            }
            mA = fmaxf(mA, __shfl_xor_sync(FULL, mA, 1));
            mA = fmaxf(mA, __shfl_xor_sync(FULL, mA, 2));
            mB = fmaxf(mB, __shfl_xor_sync(FULL, mB, 1));
            mB = fmaxf(mB, __shfl_xor_sync(FULL, mB, 2));
            float sA = 0.f, sB = 0.f;
#pragma unroll
            for (int j = 0; j < 3; j++) {
                acc[mi][j][0] = __expf(acc[mi][j][0] - mA);
                acc[mi][j][1] = __expf(acc[mi][j][1] - mA);
                acc[mi][j][2] = __expf(acc[mi][j][2] - mB);
                acc[mi][j][3] = __expf(acc[mi][j][3] - mB);
                sA += acc[mi][j][0] + acc[mi][j][1];
                sB += acc[mi][j][2] + acc[mi][j][3];
            }
            sA += __shfl_xor_sync(FULL, sA, 1);
            sA += __shfl_xor_sync(FULL, sA, 2);
            sB += __shfl_xor_sync(FULL, sB, 1);
            sB += __shfl_xor_sync(FULL, sB, 2);
            float iA = 1.f / sA, iB = 1.f / sB;
#pragma unroll
            for (int j = 0; j < 3; j++) {
                int col = w * 24 + j * 8 + 2 * tig;
                int q = q0 + mi * 16 + g;
                *(float2*)&g_attn[q * 192 + col] =
                    make_float2(acc[mi][j][0] * iA, acc[mi][j][1] * iA);
                *(float2*)&g_attn[(q + 8) * 192 + col] =
                    make_float2(acc[mi][j][2] * iB, acc[mi][j][3] * iB);
            }
        }
    }
}

// ---------------- fused desc+gather: block/query, warp/head ------------------
// Descs: uint2 per (tap,row) = {byte_off, h2(wlo,whi)}; [tap][row] layout.
// 2 taps per warp-iteration. Lane bits: b4=tap parity, b3=row, b0..2=16B seg.
// Inner: LDS.64 + PRMT + IADD + LDG.128 + 4xHFMA2; fp32 flush every 16 taps.
__global__ __launch_bounds__(256) void k_gather() {
    __shared__ __align__(16) uint2 s_desc[2304];
    __shared__ float s_off[384];
    __shared__ float s_attn[192];
    __shared__ float s_coor[12];
    __shared__ float s_mask[6];

    int q = blockIdx.x, tid = threadIdx.x;

    s_off[tid] = g_off[q * 384 + tid];
    if (tid < 128) s_off[256 + tid] = g_off[q * 384 + 256 + tid];
    if (tid < 192) s_attn[tid] = g_attn[q * 192 + tid];
    if (tid < 12)  s_coor[tid] = g_coor[((tid >> 1) * NQ + q) * 2 + (tid & 1)];
    if (tid < 6)   s_mask[tid] = g_mask[tid * NQ + q];
    __syncthreads();

    int h = tid >> 5, lane = tid & 31;

    float cnt = s_mask[0] + s_mask[1] + s_mask[2] + s_mask[3] + s_mask[4] + s_mask[5];
    float inv = 1.f / fmaxf(cnt, 1.f);

    const int lw[3]  = {176, 88, 44};
    const int lhh[3] = {64, 32, 16};
    const int lst[3] = {0, 11264, 14080};

    for (int i = lane; i < 144; i += 32) {
        int cam = i / 24, l = (i >> 3) % 3, p = i & 7;
        int w = lw[l], hh = lhh[l];
        float cx = s_coor[cam * 2], cy = s_coor[cam * 2 + 1];
        int oi = ((h * 3 + l) * 8 + p) * 2;
        float x = cx * (float)w  - 0.5f + s_off[oi];
        float y = cy * (float)hh - 0.5f + s_off[oi + 1];
        float am = s_attn[h * 24 + l * 8 + p] * s_mask[cam] * inv;

        float xf = floorf(x), yf = floorf(y);
        float tx = x - xf, ty = y - yf;
        int x0 = (int)xf, y0 = (int)yf;
        float wx0 = ((x0 >= 0) && (x0 < w)) ? (1.f - tx) : 0.f;
        float wx1 = ((x0 + 1 >= 0) && (x0 + 1 < w)) ? tx : 0.f;
        int xb = min(max(x0, 0), w - 2);
        float wlo = (xb == x0) ? wx0 : ((xb == x0 + 1) ? wx1 : 0.f);
        float whi = (xb == x0) ? wx1 : ((xb == x0 - 1) ? wx0 : 0.f);

        unsigned base = (unsigned)((cam * 8 + h) * STOT + lst[l] + xb);
        {
            int r = y0;
            float wy = ((r >= 0) && (r < hh)) ? (1.f - ty) : 0.f;
            int rr = min(max(r, 0), hh - 1);
            uint2 d;
            d.x = (base + (unsigned)(rr * w)) * 64u;           // byte offset
            d.y = pack_h2(am * wy * wlo, am * wy * whi);
            s_desc[(h * 144 + i) * 2 + 0] = d;
        }
        {
            int r = y0 + 1;
            float wy = ((r >= 0) && (r < hh)) ? ty : 0.f;
            int rr = min(max(r, 0), hh - 1);
            uint2 d;
            d.x = (base + (unsigned)(rr * w)) * 64u;
            d.y = pack_h2(am * wy * wlo, am * wy * whi);
            s_desc[(h * 144 + i) * 2 + 1] = d;
        }
    }
    __syncwarp();

    int t16 = lane >> 4;            // tap parity
    int r8  = (lane >> 3) & 1;      // row
    int lc  = lane & 7;             // 16B segment (8 channels); x-col = lc>>2
    unsigned laneconst = (unsigned)(lc * 16);                  // bytes
    unsigned wsel = (lc >= 4) ? 0x3232u : 0x1010u;             // bcast whi / wlo
    const uint2* dp = s_desc + h * 288 + 2 * t16 + r8;
    const char* vb = (const char*)g_value;

    float a0 = 0.f, a1 = 0.f, a2 = 0.f, a3 = 0.f;
    float a4 = 0.f, a5 = 0.f, a6 = 0.f, a7 = 0.f;
#pragma unroll 1
    for (int grp = 0; grp < 9; grp++) {
        __half2 h0 = __floats2half2_rn(0.f, 0.f);
        __half2 h1 = h0, h2 = h0, h3 = h0;
#pragma unroll
        for (int k = 0; k < 8; k++) {
            uint2 d = dp[(grp * 8 + k) * 4];
            unsigned wp;
            asm("prmt.b32 %0, %1, %1, %2;" : "=r"(wp) : "r"(d.y), "r"(wsel));
            uint4 v = *(const uint4*)(vb + d.x + laneconst);
            h0 = __hfma2(*(__half2*)&v.x, *(__half2*)&wp, h0);
            h1 = __hfma2(*(__half2*)&v.y, *(__half2*)&wp, h1);
            h2 = __hfma2(*(__half2*)&v.z, *(__half2*)&wp, h2);
            h3 = __hfma2(*(__half2*)&v.w, *(__half2*)&wp, h3);
        }
        float2 f0 = __half22float2(h0);
        float2 f1 = __half22float2(h1);
        float2 f2 = __half22float2(h2);
        float2 f3 = __half22float2(h3);
        a0 += f0.x; a1 += f0.y; a2 += f1.x; a3 += f1.y;
        a4 += f2.x; a5 += f2.y; a6 += f3.x; a7 += f3.y;
    }

    const unsigned FULL = 0xFFFFFFFFu;
#pragma unroll
    for (int o = 4; o <= 16; o <<= 1) {
        a0 += __shfl_xor_sync(FULL, a0, o);
        a1 += __shfl_xor_sync(FULL, a1, o);
        a2 += __shfl_xor_sync(FULL, a2, o);
        a3 += __shfl_xor_sync(FULL, a3, o);
        a4 += __shfl_xor_sync(FULL, a4, o);
        a5 += __shfl_xor_sync(FULL, a5, o);
        a6 += __shfl_xor_sync(FULL, a6, o);
        a7 += __shfl_xor_sync(FULL, a7, o);
    }

    if (lane < 4) {
        float* sp = &g_slots[q * 256 + h * 32 + lane * 8];
        *(float4*)sp       = make_float4(a0, a1, a2, a3);
        *(float4*)(sp + 4) = make_float4(a4, a5, a6, a7);
    }
}

// ---------------- out projection via fp16 mma + residual + LayerNorm ---------
__global__ __launch_bounds__(256) void k_outln(
        const float* __restrict__ feature,
        const float* __restrict__ b_out,
        const float* __restrict__ ln_g, const float* __restrict__ ln_b,
        float* __restrict__ out) {
    __shared__ __half As[64 * 72];
    __shared__ __half Bs[256 * 72];
    __shared__ float red_s[64 * 8];
    __shared__ float red2_s[64 * 8];

    int q0 = blockIdx.x * 64;
    int tid = threadIdx.x;
    int w = tid >> 5, lane = tid & 31;
    int g = lane >> 2, tig = lane & 3;

    float acc[4][4][4];
#pragma unroll
    for (int j = 0; j < 4; j++) {
        int col = w * 32 + j * 8 + 2 * tig;
        float bv0 = b_out[col], bv1 = b_out[col + 1];
#pragma unroll
        for (int mi = 0; mi < 4; mi++) {
            acc[mi][j][0] = bv0; acc[mi][j][1] = bv1;
            acc[mi][j][2] = bv0; acc[mi][j][3] = bv1;
        }
    }

    for (int kc = 0; kc < 4; kc++) {
        __syncthreads();
#pragma unroll
        for (int i = 0; i < 8; i++) {
            int row = w * 8 + i;
            const float2 f = *(const float2*)&g_slots[(q0 + row) * 256 + kc * 64 + 2 * lane];
            *(unsigned*)&As[row * 72 + 2 * lane] = pack_h2(f.x, f.y);
        }
#pragma unroll
        for (int t = 0; t < 16; t++) {
            int e = t * 256 + tid;
            int n = e >> 4, seg = e & 15;
            *(unsigned long long*)&Bs[n * 72 + seg * 4] =
                *(const unsigned long long*)&g_WoT[n * 256 + kc * 64 + seg * 4];
        }
        __syncthreads();
#pragma unroll
        for (int ks = 0; ks < 4; ks++) {
            int k2 = ks * 8;
            const unsigned* Ap = (const unsigned*)As;
            const unsigned* Bp = (const unsigned*)Bs;
            unsigned a[4][4];
#pragma unroll
            for (int mi = 0; mi < 4; mi++) {
                int r = mi * 16 + g;
                a[mi][0] = Ap[r * 36 + k2 + tig];
                a[mi][1] = Ap[(r + 8) * 36 + k2 + tig];
                a[mi][2] = Ap[r * 36 + k2 + 4 + tig];
                a[mi][3] = Ap[(r + 8) * 36 + k2 + 4 + tig];
            }
#pragma unroll
            for (int j = 0; j < 4; j++) {
                int n = w * 32 + j * 8 + g;
                unsigned b0 = Bp[n * 36 + k2 + tig];
                unsigned b1 = Bp[n * 36 + k2 + 4 + tig];
#pragma unroll
                for (int mi = 0; mi < 4; mi++)
                    mma16816(acc[mi][j], a[mi][0], a[mi][1], a[mi][2], a[mi][3], b0, b1);
            }
        }
    }

    const unsigned FULL = 0xFFFFFFFFu;
#pragma unroll
    for (int mi = 0; mi < 4; mi++) {
        float s0 = 0.f, s1 = 0.f, ss0 = 0.f, ss1 = 0.f;
#pragma unroll
        for (int j = 0; j < 4; j++) {
            int col = w * 32 + j * 8 + 2 * tig;
            int q = q0 + mi * 16 + g;
            float2 fA = *(const float2*)&feature[q * 256 + col];
            float2 fB = *(const float2*)&feature[(q + 8) * 256 + col];
            acc[mi][j][0] += fA.x; acc[mi][j][1] += fA.y;
            acc[mi][j][2] += fB.x; acc[mi][j][3] += fB.y;
            s0  += acc[mi][j][0] + acc[mi][j][1];
            s1  += acc[mi][j][2] + acc[mi][j][3];
            ss0 += acc[mi][j][0] * acc[mi][j][0] + acc[mi][j][1] * acc[mi][j][1];
            ss1 += acc[mi][j][2] * acc[mi][j][2] + acc[mi][j][3] * acc[mi][j][3];
        }
        s0  += __shfl_xor_sync(FULL, s0, 1);  s0  += __shfl_xor_sync(FULL, s0, 2);
        s1  += __shfl_xor_sync(FULL, s1, 1);  s1  += __shfl_xor_sync(FULL, s1, 2);
        ss0 += __shfl_xor_sync(FULL, ss0, 1); ss0 += __shfl_xor_sync(FULL, ss0, 2);
        ss1 += __shfl_xor_sync(FULL, ss1, 1); ss1 += __shfl_xor_sync(FULL, ss1, 2);
        if (tig == 0) {
            red_s [(mi * 16 + g) * 8 + w] = s0;
            red_s [(mi * 16 + 8 + g) * 8 + w] = s1;
            red2_s[(mi * 16 + g) * 8 + w] = ss0;
            red2_s[(mi * 16 + 8 + g) * 8 + w] = ss1;
        }
    }
    __syncthreads();

#pragma unroll
    for (int mi = 0; mi < 4; mi++) {
        float sum0 = 0.f, sum1 = 0.f, sq0 = 0.f, sq1 = 0.f;
#pragma unroll
        for (int ww = 0; ww < 8; ww++) {
            sum0 += red_s [(mi * 16 + g) * 8 + ww];
            sum1 += red_s [(mi * 16 + 8 + g) * 8 + ww];
            sq0  += red2_s[(mi * 16 + g) * 8 + ww];
            sq1  += red2_s[(mi * 16 + 8 + g) * 8 + ww];
        }
        float mu0 = sum0 * (1.f / 256.f), mu1 = sum1 * (1.f / 256.f);
        float rv0 = rsqrtf(sq0 * (1.f / 256.f) - mu0 * mu0 + 1e-5f);
        float rv1 = rsqrtf(sq1 * (1.f / 256.f) - mu1 * mu1 + 1e-5f);
#pragma unroll
        for (int j = 0; j < 4; j++) {
            int col = w * 32 + j * 8 + 2 * tig;
            int q = q0 + mi * 16 + g;
            float2 gg = *(const float2*)&ln_g[col];
            float2 bb = *(const float2*)&ln_b[col];
            *(float2*)&out[q * 256 + col] = make_float2(
                (acc[mi][j][0] - mu0) * rv0 * gg.x + bb.x,
                (acc[mi][j][1] - mu0) * rv0 * gg.y + bb.y);
            *(float2*)&out[(q + 8) * 256 + col] = make_float2(
                (acc[mi][j][2] - mu1) * rv1 * gg.x + bb.x,
                (acc[mi][j][3] - mu1) * rv1 * gg.y + bb.y);
        }
    }
}

// ---------------- launch: prep -> fork(value | offattn) -> gather -> outln ---
extern "C" void kernel_launch(void* const* d_in, const int* in_sizes, int n_in,
                              void* d_out, int out_size) {
    const float* means      = (const float*)d_in[0];
    const float* feature    = (const float*)d_in[1];
    const float* feat0      = (const float*)d_in[2];
    const float* feat1      = (const float*)d_in[3];
    const float* feat2      = (const float*)d_in[4];
    const float* cam2ego    = (const float*)d_in[5];
    const float* intrins    = (const float*)d_in[6];
    const float* post_rots  = (const float*)d_in[7];
    const float* post_trans = (const float*)d_in[8];
    const float* W_off      = (const float*)d_in[9];
    const float* b_off      = (const float*)d_in[10];
    const float* W_attn     = (const float*)d_in[11];
    const float* b_attn     = (const float*)d_in[12];
    const float* W_val      = (const float*)d_in[13];
    const float* b_val      = (const float*)d_in[14];
    const float* W_out      = (const float*)d_in[15];
    const float* b_out      = (const float*)d_in[16];
    const float* ce         = (const float*)d_in[17];
    const float* le         = (const float*)d_in[18];
    const float* ln_g       = (const float*)d_in[19];
    const float* ln_b       = (const float*)d_in[20];
    float* out = (float*)d_out;

    cudaStream_t s1;
    cudaEvent_t ePrep, eValue;
    cudaStreamCreateWithFlags(&s1, cudaStreamNonBlocking);
    cudaEventCreateWithFlags(&ePrep,  cudaEventDisableTiming);
    cudaEventCreateWithFlags(&eValue, cudaEventDisableTiming);

    // 1) prep (+projinv) on main
    k_prep<<<440, 256>>>(W_val, W_off, W_attn, W_out, ce, le,
                         cam2ego, means, intrins, post_rots, post_trans);
    cudaEventRecord(ePrep, 0);

    // 2) value on s1 (after prep), offattn on main
    cudaStreamWaitEvent(s1, ePrep, 0);
    k_value<<<1386, 256, 0, s1>>>(feat0, feat1, feat2, b_val);
    cudaEventRecord(eValue, s1);

    k_offattn<<<dim3(100, 3), 256>>>(feature, b_off, b_attn);

    // 3) join: gather (launch #4), then outln
    cudaStreamWaitEvent(0, eValue, 0);
    k_gather<<<NQ, 256>>>();
    k_outln<<<100, 256>>>(feature, b_out, ln_g, ln_b, out);
}

// round 16
// speedup vs baseline: 1.0797x; 1.0054x over previous
#include <cuda_runtime.h>
#include <cuda_fp16.h>
#include <math.h>

#define NC   6
#define NH   8
#define NL   3
#define NPT  8
#define CDIM 256
#define DDIM 32
#define NQ   6400
#define STOT 14784   // 64*176 + 32*88 + 16*44

// ---------------- scratch (device globals; no allocations allowed) ----------
__device__ float  g_coor[NC * NQ * 2];
__device__ float  g_mask[NC * NQ];
__device__ float  g_off [NQ * 384];
__device__ float  g_attn[NQ * 192];
__device__ float  g_slots[NQ * CDIM];
__device__ __align__(16) __half g_WhT [CDIM * CDIM];        // W_val^T [n][k]
__device__ __align__(16) __half g_WoaT[576 * CDIM];         // [W_off|W_attn]^T [n][k]
__device__ __align__(16) __half g_WoT [CDIM * CDIM];        // W_out^T [n][k]
__device__ float  g_embsum[NC * NL * CDIM];                 // cams+level embeds
__device__ __align__(16) __half g_value[(size_t)NC * NH * STOT * DDIM];  // 45.4 MB fp16

// ---------------- fp16 mma helper -------------------------------------------
__device__ __forceinline__ void mma16816(float* c,
    unsigned a0, unsigned a1, unsigned a2, unsigned a3,
    unsigned b0, unsigned b1) {
    asm volatile(
        "mma.sync.aligned.m16n8k16.row.col.f32.f16.f16.f32 "
        "{%0,%1,%2,%3}, {%4,%5,%6,%7}, {%8,%9}, {%0,%1,%2,%3};"
        : "+f"(c[0]), "+f"(c[1]), "+f"(c[2]), "+f"(c[3])
        : "r"(a0), "r"(a1), "r"(a2), "r"(a3), "r"(b0), "r"(b1));
}
__device__ __forceinline__ unsigned pack_h2(float a, float b) {
    __half2 h = __floats2half2_rn(a, b);
    return *(unsigned*)&h;
}

// ---------------- prep+projinv: one kernel, block-range dispatch --------------
__global__ __launch_bounds__(256) void k_prep(
        const float* __restrict__ W_val,
        const float* __restrict__ W_off,
        const float* __restrict__ W_attn,
        const float* __restrict__ W_out,
        const float* __restrict__ ce,
        const float* __restrict__ le,
        const float* __restrict__ cam2ego,
        const float* __restrict__ means,
        const float* __restrict__ intrins,
        const float* __restrict__ post_rots,
        const float* __restrict__ post_trans) {
    int b = blockIdx.x;
    int tid = threadIdx.x;
    if (b < 272) {
        __shared__ float ts[32][33];
        int kt, nt;
        if (b < 64)       { kt = b / 8;         nt = b % 8; }
        else if (b < 208) { kt = (b - 64) / 18; nt = (b - 64) % 18; }
        else              { kt = (b - 208) / 8; nt = (b - 208) % 8; }
        int w = tid >> 5, lane = tid & 31;
#pragma unroll
        for (int it = 0; it < 4; it++) {
            int r = it * 8 + w;
            int k = kt * 32 + r;
            int n = nt * 32 + lane;
            float v;
            if (b < 64)       v = W_val[k * 256 + n];
            else if (b < 208) v = (n < 384) ? W_off[k * 384 + n] : W_attn[k * 192 + (n - 384)];
            else              v = W_out[k * 256 + n];
            ts[r][lane] = v;
        }
        __syncthreads();
#pragma unroll
        for (int it = 0; it < 4; it++) {
            int r = it * 8 + w;
            int n = nt * 32 + r;
            int k = kt * 32 + lane;
            __half hv = __float2half(ts[lane][r]);
            if (b < 64)       g_WhT [n * 256 + k] = hv;
            else if (b < 208) g_WoaT[n * 256 + k] = hv;
            else              g_WoT [n * 256 + k] = hv;
        }
    } else if (b < 290) {
        int idx = (b - 272) * 256 + tid;
        if (idx < NC * NL * CDIM) {
            int cl = idx >> 8, c = idx & 255;
            g_embsum[idx] = ce[(cl / 3) * 256 + c] + le[(cl % 3) * 256 + c];
        }
    } else {
        __shared__ float inv_s[NC * 16];
        if (tid < NC) {
            int c = tid;
            float a[4][8];
            for (int r = 0; r < 4; r++)
                for (int j = 0; j < 4; j++) {
                    a[r][j]     = cam2ego[c * 16 + r * 4 + j];
                    a[r][4 + j] = (r == j) ? 1.f : 0.f;
                }
            for (int col = 0; col < 4; col++) {
                int piv = col; float mxv = fabsf(a[col][col]);
                for (int r = col + 1; r < 4; r++) {
                    float vv = fabsf(a[r][col]);
                    if (vv > mxv) { mxv = vv; piv = r; }
                }
                if (piv != col)
                    for (int j = 0; j < 8; j++) { float t = a[col][j]; a[col][j] = a[piv][j]; a[piv][j] = t; }
                float ivp = 1.f / a[col][col];
                for (int j = 0; j < 8; j++) a[col][j] *= ivp;
                for (int r = 0; r < 4; r++) if (r != col) {
                    float f = a[r][col];
                    for (int j = 0; j < 8; j++) a[r][j] -= f * a[col][j];
                }
            }
            for (int r = 0; r < 4; r++)
                for (int j = 0; j < 4; j++)
                    inv_s[c * 16 + r * 4 + j] = a[r][4 + j];
        }
        __syncthreads();

        int idx = (b - 290) * 256 + tid;     // < 38400
        int cam = idx / NQ, q = idx % NQ;
        float mx = means[q * 3 + 0], my = means[q * 3 + 1], mz = means[q * 3 + 2];
        const float* M = inv_s + cam * 16;
        float X = M[0] * mx + M[1] * my + M[2]  * mz + M[3];
        float Y = M[4] * mx + M[5] * my + M[6]  * mz + M[7];
        float Z = M[8] * mx + M[9] * my + M[10] * mz + M[11];
        const float* I = intrins + cam * 9;
        float u  = I[0] * X + I[1] * Y + I[2] * Z;
        float v  = I[3] * X + I[4] * Y + I[5] * Z;
        float zz = I[6] * X + I[7] * Y + I[8] * Z;
        float iz = 1.f / (zz + 1e-4f);
        float m0 = u * iz, m1 = v * iz, m2 = zz;
        const float* P = post_rots + cam * 9;
        const float* T = post_trans + cam * 3;
        float px = P[0] * m0 + P[1] * m1 + P[2] * m2 + T[0];
        float py = P[3] * m0 + P[4] * m1 + P[5] * m2 + T[1];
        float pz = P[6] * m0 + P[7] * m1 + P[8] * m2 + T[2];
        float cx = px / 1408.0f;
        float cy = py / 512.0f;
        bool msk = (pz > 0.01f) && (cx > 0.f) && (cx < 1.f) && (cy > 0.f) && (cy < 1.f);
        g_coor[idx * 2 + 0] = cx;
        g_coor[idx * 2 + 1] = cy;
        g_mask[idx] = msk ? 1.f : 0.f;
    }
}

// ---------------- value build + GEMM via fp16 mma ----------------------------
__global__ __launch_bounds__(256) void k_value(
        const float* __restrict__ feat0,
        const float* __restrict__ feat1,
        const float* __restrict__ feat2,
        const float* __restrict__ b_val) {
    __shared__ __half As[64 * 72];
    __shared__ __half Bs[256 * 72];

    int bx = blockIdx.x;
    int cam = bx / 231, rb = bx % 231;
    int lvl, hw, pix0; const float* fb;
    if (rb < 176)      { lvl = 0; hw = 11264; pix0 = rb * 64;          fb = feat0; }
    else if (rb < 220) { lvl = 1; hw = 2816;  pix0 = (rb - 176) * 64;  fb = feat1; }
    else               { lvl = 2; hw = 704;   pix0 = (rb - 220) * 64;  fb = feat2; }
    fb += (size_t)cam * CDIM * hw;
    int m0 = rb * 64;
    const float* emb = g_embsum + (cam * 3 + lvl) * 256;

    int tid = threadIdx.x;
    int w = tid >> 5, lane = tid & 31;
    int g = lane >> 2, tig = lane & 3;

    float acc[4][4][4];
#pragma unroll
    for (int j = 0; j < 4; j++) {
        int d = j * 8 + 2 * tig;
        float bv0 = b_val[w * 32 + d], bv1 = b_val[w * 32 + d + 1];
#pragma unroll
        for (int mi = 0; mi < 4; mi++) {
            acc[mi][j][0] = bv0; acc[mi][j][1] = bv1;
            acc[mi][j][2] = bv0; acc[mi][j][3] = bv1;
        }
    }

    for (int kc = 0; kc < 4; kc++) {
        __syncthreads();
#pragma unroll
        for (int i = 0; i < 4; i++) {
            int cp = w * 4 + i;
            int c = kc * 64 + cp * 2;
            float e0 = emb[c], e1 = emb[c + 1];
#pragma unroll
            for (int j = 0; j < 2; j++) {
                int pix = lane + 32 * j;
                float f0 = fb[(size_t)c * hw + pix0 + pix] + e0;
                float f1 = fb[(size_t)(c + 1) * hw + pix0 + pix] + e1;
                *(unsigned*)&As[pix * 72 + cp * 2] = pack_h2(f0, f1);
            }
        }
#pragma unroll
        for (int t = 0; t < 16; t++) {
            int e = t * 256 + tid;
            int n = e >> 4, seg = e & 15;
            *(unsigned long long*)&Bs[n * 72 + seg * 4] =
                *(const unsigned long long*)&g_WhT[n * 256 + kc * 64 + seg * 4];
        }
        __syncthreads();
#pragma unroll
        for (int ks = 0; ks < 4; ks++) {
            int k2 = ks * 8;
            const unsigned* Ap = (const unsigned*)As;
            const unsigned* Bp = (const unsigned*)Bs;
            unsigned a[4][4];
#pragma unroll
            for (int mi = 0; mi < 4; mi++) {
                int r = mi * 16 + g;
                a[mi][0] = Ap[r * 36 + k2 + tig];
                a[mi][1] = Ap[(r + 8) * 36 + k2 + tig];
                a[mi][2] = Ap[r * 36 + k2 + 4 + tig];
                a[mi][3] = Ap[(r + 8) * 36 + k2 + 4 + tig];
            }
#pragma unroll
            for (int j = 0; j < 4; j++) {
                int n = w * 32 + j * 8 + g;
                unsigned b0 = Bp[n * 36 + k2 + tig];
                unsigned b1 = Bp[n * 36 + k2 + 4 + tig];
#pragma unroll
                for (int mi = 0; mi < 4; mi++)
                    mma16816(acc[mi][j], a[mi][0], a[mi][1], a[mi][2], a[mi][3], b0, b1);
            }
        }
    }
    size_t vbase = ((size_t)(cam * 8 + w) * STOT) * 32;
#pragma unroll
    for (int mi = 0; mi < 4; mi++)
#pragma unroll
        for (int j = 0; j < 4; j++) {
            int d = j * 8 + 2 * tig;
            int s = m0 + mi * 16 + g;
            *(unsigned*)&g_value[vbase + (size_t)s * 32 + d] = pack_h2(acc[mi][j][0], acc[mi][j][1]);
            *(unsigned*)&g_value[vbase + (size_t)(s + 8) * 32 + d] = pack_h2(acc[mi][j][2], acc[mi][j][3]);
        }
}

// ---------------- offsets+attn GEMM via fp16 mma, softmax fused --------------
__global__ __launch_bounds__(256) void k_offattn(
        const float* __restrict__ feature,
        const float* __restrict__ b_off, const float* __restrict__ b_attn) {
    __shared__ __half As[64 * 72];
    __shared__ __half Bs[192 * 72];

    int q0 = blockIdx.x * 64;
    int ny = blockIdx.y;           // 0..2
    int tid = threadIdx.x;
    int w = tid >> 5, lane = tid & 31;
    int g = lane >> 2, tig = lane & 3;

    float acc[4][3][4];
#pragma unroll
    for (int j = 0; j < 3; j++) {
        int col = ny * 192 + w * 24 + j * 8 + 2 * tig;
        float bv0 = (col < 384) ? b_off[col] : b_attn[col - 384];
        float bv1 = (col + 1 < 384) ? b_off[col + 1] : b_attn[col + 1 - 384];
#pragma unroll
        for (int mi = 0; mi < 4; mi++) {
            acc[mi][j][0] = bv0; acc[mi][j][1] = bv1;
            acc[mi][j][2] = bv0; acc[mi][j][3] = bv1;
        }
    }

    for (int kc = 0; kc < 4; kc++) {
        __syncthreads();
#pragma unroll
        for (int i = 0; i < 8; i++) {
            int row = w * 8 + i;
            const float2 f = *(const float2*)&feature[(q0 + row) * 256 + kc * 64 + 2 * lane];
            *(unsigned*)&As[row * 72 + 2 * lane] = pack_h2(f.x, f.y);
        }
#pragma unroll
        for (int t = 0; t < 12; t++) {
            int e = t * 256 + tid;
            int n = e >> 4, seg = e & 15;
            *(unsigned long long*)&Bs[n * 72 + seg * 4] =
                *(const unsigned long long*)&g_WoaT[(ny * 192 + n) * 256 + kc * 64 + seg * 4];
        }
        __syncthreads();
#pragma unroll
        for (int ks = 0; ks < 4; ks++) {
            int k2 = ks * 8;
            const unsigned* Ap = (const unsigned*)As;
            const unsigned* Bp = (const unsigned*)Bs;
            unsigned a[4][4];
#pragma unroll
            for (int mi = 0; mi < 4; mi++) {
                int r = mi * 16 + g;
                a[mi][0] = Ap[r * 36 + k2 + tig];
                a[mi][1] = Ap[(r + 8) * 36 + k2 + tig];
                a[mi][2] = Ap[r * 36 + k2 + 4 + tig];
                a[mi][3] = Ap[(r + 8) * 36 + k2 + 4 + tig];
            }
#pragma unroll
            for (int j = 0; j < 3; j++) {
                int n = w * 24 + j * 8 + g;
                unsigned b0 = Bp[n * 36 + k2 + tig];
                unsigned b1 = Bp[n * 36 + k2 + 4 + tig];
#pragma unroll
                for (int mi = 0; mi < 4; mi++)
                    mma16816(acc[mi][j], a[mi][0], a[mi][1], a[mi][2], a[mi][3], b0, b1);
            }
        }
    }

    if (ny < 2) {
#pragma unroll
        for (int mi = 0; mi < 4; mi++)
#pragma unroll
            for (int j = 0; j < 3; j++) {
                int col = ny * 192 + w * 24 + j * 8 + 2 * tig;
                int q = q0 + mi * 16 + g;
                *(float2*)&g_off[q * 384 + col] = make_float2(acc[mi][j][0], acc[mi][j][1]);
                *(float2*)&g_off[(q + 8) * 384 + col] = make_float2(acc[mi][j][2], acc[mi][j][3]);
            }
    } else {
        const unsigned FULL = 0xFFFFFFFFu;
#pragma unroll
        for (int mi = 0; mi < 4; mi++) {
            float mA = -1e30f, mB = -1e30f;
#pragma unroll
            for (int j = 0; j < 3; j++) {
                mA = fmaxf(mA, fmaxf(acc[mi][j][0], acc[mi][j][1]));
                mB = fmaxf(mB, fmaxf(acc[mi][j][2], acc[mi][j][3]));
            }
            mA = fmaxf(mA, __shfl_xor_sync(FULL, mA, 1));
            mA = fmaxf(mA, __shfl_xor_sync(FULL, mA, 2));
            mB = fmaxf(mB, __shfl_xor_sync(FULL, mB, 1));
            mB = fmaxf(mB, __shfl_xor_sync(FULL, mB, 2));
            float sA = 0.f, sB = 0.f;
#pragma unroll
            for (int j = 0; j < 3; j++) {
                acc[mi][j][0] = __expf(acc[mi][j][0] - mA);
                acc[mi][j][1] = __expf(acc[mi][j][1] - mA);
                acc[mi][j][2] = __expf(acc[mi][j][2] - mB);
                acc[mi][j][3] = __expf(acc[mi][j][3] - mB);
                sA += acc[mi][j][0] + acc[mi][j][1];
                sB += acc[mi][j][2] + acc[mi][j][3];
            }
            sA += __shfl_xor_sync(FULL, sA, 1);
            sA += __shfl_xor_sync(FULL, sA, 2);
            sB += __shfl_xor_sync(FULL, sB, 1);
            sB += __shfl_xor_sync(FULL, sB, 2);
            float iA = 1.f / sA, iB = 1.f / sB;
#pragma unroll
            for (int j = 0; j < 3; j++) {
                int col = w * 24 + j * 8 + 2 * tig;
                int q = q0 + mi * 16 + g;
                *(float2*)&g_attn[q * 192 + col] =
                    make_float2(acc[mi][j][0] * iA, acc[mi][j][1] * iA);
                *(float2*)&g_attn[(q + 8) * 192 + col] =
                    make_float2(acc[mi][j][2] * iB, acc[mi][j][3] * iB);
            }
        }
    }
}

// ---------------- fused desc+gather: block/query, warp/head ------------------
__global__ __launch_bounds__(256) void k_gather() {
    __shared__ __align__(16) uint2 s_desc[2304];
    __shared__ float s_off[384];
    __shared__ float s_attn[192];
    __shared__ float s_coor[12];
    __shared__ float s_mask[6];

    int q = blockIdx.x, tid = threadIdx.x;

    s_off[tid] = g_off[q * 384 + tid];
    if (tid < 128) s_off[256 + tid] = g_off[q * 384 + 256 + tid];
    if (tid < 192) s_attn[tid] = g_attn[q * 192 + tid];
    if (tid < 12)  s_coor[tid] = g_coor[((tid >> 1) * NQ + q) * 2 + (tid & 1)];
    if (tid < 6)   s_mask[tid] = g_mask[tid * NQ + q];
    __syncthreads();

    int h = tid >> 5, lane = tid & 31;

    float cnt = s_mask[0] + s_mask[1] + s_mask[2] + s_mask[3] + s_mask[4] + s_mask[5];
    float inv = 1.f / fmaxf(cnt, 1.f);

    const int lw[3]  = {176, 88, 44};
    const int lhh[3] = {64, 32, 16};
    const int lst[3] = {0, 11264, 14080};

    for (int i = lane; i < 144; i += 32) {
        int cam = i / 24, l = (i >> 3) % 3, p = i & 7;
        int w = lw[l], hh = lhh[l];
        float cx = s_coor[cam * 2], cy = s_coor[cam * 2 + 1];
        int oi = ((h * 3 + l) * 8 + p) * 2;
        float x = cx * (float)w  - 0.5f + s_off[oi];
        float y = cy * (float)hh - 0.5f + s_off[oi + 1];
        float am = s_attn[h * 24 + l * 8 + p] * s_mask[cam] * inv;

        float xf = floorf(x), yf = floorf(y);
        float tx = x - xf, ty = y - yf;
        int x0 = (int)xf, y0 = (int)yf;
        float wx0 = ((x0 >= 0) && (x0 < w)) ? (1.f - tx) : 0.f;
        float wx1 = ((x0 + 1 >= 0) && (x0 + 1 < w)) ? tx : 0.f;
        int xb = min(max(x0, 0), w - 2);
        float wlo = (xb == x0) ? wx0 : ((xb == x0 + 1) ? wx1 : 0.f);
        float whi = (xb == x0) ? wx1 : ((xb == x0 - 1) ? wx0 : 0.f);

        unsigned base = (unsigned)((cam * 8 + h) * STOT + lst[l] + xb);
        {
            int r = y0;
            float wy = ((r >= 0) && (r < hh)) ? (1.f - ty) : 0.f;
            int rr = min(max(r, 0), hh - 1);
            uint2 d;
            d.x = (base + (unsigned)(rr * w)) * 64u;           // byte offset
            d.y = pack_h2(am * wy * wlo, am * wy * whi);
            s_desc[(h * 144 + i) * 2 + 0] = d;
        }
        {
            int r = y0 + 1;
            float wy = ((r >= 0) && (r < hh)) ? ty : 0.f;
            int rr = min(max(r, 0), hh - 1);
            uint2 d;
            d.x = (base + (unsigned)(rr * w)) * 64u;
            d.y = pack_h2(am * wy * wlo, am * wy * whi);
            s_desc[(h * 144 + i) * 2 + 1] = d;
        }
    }
    __syncwarp();

    int t16 = lane >> 4;            // tap parity
    int r8  = (lane >> 3) & 1;      // row
    int lc  = lane & 7;             // 16B segment (8 channels); x-col = lc>>2
    unsigned laneconst = (unsigned)(lc * 16);                  // bytes
    unsigned wsel = (lc >= 4) ? 0x3232u : 0x1010u;             // bcast whi / wlo
    const uint2* dp = s_desc + h * 288 + 2 * t16 + r8;
    const char* vb = (const char*)g_value;

    float a0 = 0.f, a1 = 0.f, a2 = 0.f, a3 = 0.f;
    float a4 = 0.f, a5 = 0.f, a6 = 0.f, a7 = 0.f;
#pragma unroll 1
    for (int grp = 0; grp < 9; grp++) {
        __half2 h0 = __floats2half2_rn(0.f, 0.f);
        __half2 h1 = h0, h2 = h0, h3 = h0;
#pragma unroll
        for (int k = 0; k < 8; k++) {
            uint2 d = dp[(grp * 8 + k) * 4];
            unsigned wp;
            asm("prmt.b32 %0, %1, %1, %2;" : "=r"(wp) : "r"(d.y), "r"(wsel));
            uint4 v = *(const uint4*)(vb + d.x + laneconst);
            h0 = __hfma2(*(__half2*)&v.x, *(__half2*)&wp, h0);
            h1 = __hfma2(*(__half2*)&v.y, *(__half2*)&wp, h1);
            h2 = __hfma2(*(__half2*)&v.z, *(__half2*)&wp, h2);
            h3 = __hfma2(*(__half2*)&v.w, *(__half2*)&wp, h3);
        }
        float2 f0 = __half22float2(h0);
        float2 f1 = __half22float2(h1);
        float2 f2 = __half22float2(h2);
        float2 f3 = __half22float2(h3);
        a0 += f0.x; a1 += f0.y; a2 += f1.x; a3 += f1.y;
        a4 += f2.x; a5 += f2.y; a6 += f3.x; a7 += f3.y;
    }

    const unsigned FULL = 0xFFFFFFFFu;
#pragma unroll
    for (int o = 4; o <= 16; o <<= 1) {
        a0 += __shfl_xor_sync(FULL, a0, o);
        a1 += __shfl_xor_sync(FULL, a1, o);
        a2 += __shfl_xor_sync(FULL, a2, o);
        a3 += __shfl_xor_sync(FULL, a3, o);
        a4 += __shfl_xor_sync(FULL, a4, o);
        a5 += __shfl_xor_sync(FULL, a5, o);
        a6 += __shfl_xor_sync(FULL, a6, o);
        a7 += __shfl_xor_sync(FULL, a7, o);
    }

    if (lane < 4) {
        float* sp = &g_slots[q * 256 + h * 32 + lane * 8];
        *(float4*)sp       = make_float4(a0, a1, a2, a3);
        *(float4*)(sp + 4) = make_float4(a4, a5, a6, a7);
    }
}

// ---------------- out projection via fp16 mma + residual + LayerNorm ---------
// PDL: launched with programmatic stream serialization; stages WoT kc=0 and
// biases BEFORE cudaGridDependencySynchronize(), reads g_slots only after.
__global__ __launch_bounds__(256) void k_outln(
        const float* __restrict__ feature,
        const float* __restrict__ b_out,
        const float* __restrict__ ln_g, const float* __restrict__ ln_b,
        float* __restrict__ out) {
    __shared__ __half As[64 * 72];
    __shared__ __half Bs[256 * 72];
    __shared__ float red_s[64 * 8];
    __shared__ float red2_s[64 * 8];

    int q0 = blockIdx.x * 64;
    int tid = threadIdx.x;
    int w = tid >> 5, lane = tid & 31;
    int g = lane >> 2, tig = lane & 3;

    float acc[4][4][4];
#pragma unroll
    for (int j = 0; j < 4; j++) {
        int col = w * 32 + j * 8 + 2 * tig;
        float bv0 = b_out[col], bv1 = b_out[col + 1];
#pragma unroll
        for (int mi = 0; mi < 4; mi++) {
            acc[mi][j][0] = bv0; acc[mi][j][1] = bv1;
            acc[mi][j][2] = bv0; acc[mi][j][3] = bv1;
        }
    }

    // prologue: stage Bs for kc=0 (independent of gather output)
#pragma unroll
    for (int t = 0; t < 16; t++) {
        int e = t * 256 + tid;
        int n = e >> 4, seg = e & 15;
        *(unsigned long long*)&Bs[n * 72 + seg * 4] =
            *(const unsigned long long*)&g_WoT[n * 256 + seg * 4];
    }

    // wait for gather (prior kernel in stream) before touching g_slots
    cudaGridDependencySynchronize();

    for (int kc = 0; kc < 4; kc++) {
#pragma unroll
        for (int i = 0; i < 8; i++) {
            int row = w * 8 + i;
            const float2 f = *(const float2*)&g_slots[(q0 + row) * 256 + kc * 64 + 2 * lane];
            *(unsigned*)&As[row * 72 + 2 * lane] = pack_h2(f.x, f.y);
        }
        if (kc > 0) {
#pragma unroll
            for (int t = 0; t < 16; t++) {
                int e = t * 256 + tid;
                int n = e >> 4, seg = e & 15;
                *(unsigned long long*)&Bs[n * 72 + seg * 4] =
                    *(const unsigned long long*)&g_WoT[n * 256 + kc * 64 + seg * 4];
            }
        }
        __syncthreads();
#pragma unroll
        for (int ks = 0; ks < 4; ks++) {
            int k2 = ks * 8;
            const unsigned* Ap = (const unsigned*)As;
            const unsigned* Bp = (const unsigned*)Bs;
            unsigned a[4][4];
#pragma unroll
            for (int mi = 0; mi < 4; mi++) {
                int r = mi * 16 + g;
                a[mi][0] = Ap[r * 36 + k2 + tig];
                a[mi][1] = Ap[(r + 8) * 36 + k2 + tig];
                a[mi][2] = Ap[r * 36 + k2 + 4 + tig];
                a[mi][3] = Ap[(r + 8) * 36 + k2 + 4 + tig];
            }
#pragma unroll
            for (int j = 0; j < 4; j++) {
                int n = w * 32 + j * 8 + g;
                unsigned b0 = Bp[n * 36 + k2 + tig];
                unsigned b1 = Bp[n * 36 + k2 + 4 + tig];
#pragma unroll
                for (int mi = 0; mi < 4; mi++)
                    mma16816(acc[mi][j], a[mi][0], a[mi][1], a[mi][2], a[mi][3], b0, b1);
            }
        }
        __syncthreads();
    }

    const unsigned FULL = 0xFFFFFFFFu;
#pragma unroll
    for (int mi = 0; mi < 4; mi++) {
        float s0 = 0.f, s1 = 0.f, ss0 = 0.f, ss1 = 0.f;
#pragma unroll
        for (int j = 0; j < 4; j++) {
            int col = w * 32 + j * 8 + 2 * tig;
            int q = q0 + mi * 16 + g;
            float2 fA = *(const float2*)&feature[q * 256 + col];
            float2 fB = *(const float2*)&feature[(q + 8) * 256 + col];
            acc[mi][j][0] += fA.x; acc[mi][j][1] += fA.y;
            acc[mi][j][2] += fB.x; acc[mi][j][3] += fB.y;
            s0  += acc[mi][j][0] + acc[mi][j][1];
            s1  += acc[mi][j][2] + acc[mi][j][3];
            ss0 += acc[mi][j][0] * acc[mi][j][0] + acc[mi][j][1] * acc[mi][j][1];
            ss1 += acc[mi][j][2] * acc[mi][j][2] + acc[mi][j][3] * acc[mi][j][3];
        }
        s0  += __shfl_xor_sync(FULL, s0, 1);  s0  += __shfl_xor_sync(FULL, s0, 2);
        s1  += __shfl_xor_sync(FULL, s1, 1);  s1  += __shfl_xor_sync(FULL, s1, 2);
        ss0 += __shfl_xor_sync(FULL, ss0, 1); ss0 += __shfl_xor_sync(FULL, ss0, 2);
        ss1 += __shfl_xor_sync(FULL, ss1, 1); ss1 += __shfl_xor_sync(FULL, ss1, 2);
        if (tig == 0) {
            red_s [(mi * 16 + g) * 8 + w] = s0;
            red_s [(mi * 16 + 8 + g) * 8 + w] = s1;
            red2_s[(mi * 16 + g) * 8 + w] = ss0;
            red2_s[(mi * 16 + 8 + g) * 8 + w] = ss1;
        }
    }
    __syncthreads();

#pragma unroll
    for (int mi = 0; mi < 4; mi++) {
        float sum0 = 0.f, sum1 = 0.f, sq0 = 0.f, sq1 = 0.f;
#pragma unroll
        for (int ww = 0; ww < 8; ww++) {
            sum0 += red_s [(mi * 16 + g) * 8 + ww];
            sum1 += red_s [(mi * 16 + 8 + g) * 8 + ww];
            sq0  += red2_s[(mi * 16 + g) * 8 + ww];
            sq1  += red2_s[(mi * 16 + 8 + g) * 8 + ww];
        }
        float mu0 = sum0 * (1.f / 256.f), mu1 = sum1 * (1.f / 256.f);
        float rv0 = rsqrtf(sq0 * (1.f / 256.f) - mu0 * mu0 + 1e-5f);
        float rv1 = rsqrtf(sq1 * (1.f / 256.f) - mu1 * mu1 + 1e-5f);
#pragma unroll
        for (int j = 0; j < 4; j++) {
            int col = w * 32 + j * 8 + 2 * tig;
            int q = q0 + mi * 16 + g;
            float2 gg = *(const float2*)&ln_g[col];
            float2 bb = *(const float2*)&ln_b[col];
            *(float2*)&out[q * 256 + col] = make_float2(
                (acc[mi][j][0] - mu0) * rv0 * gg.x + bb.x,
                (acc[mi][j][1] - mu0) * rv0 * gg.y + bb.y);
            *(float2*)&out[(q + 8) * 256 + col] = make_float2(
                (acc[mi][j][2] - mu1) * rv1 * gg.x + bb.x,
                (acc[mi][j][3] - mu1) * rv1 * gg.y + bb.y);
        }
    }
}

// ---------------- launch: prep -> fork(value | offattn) -> gather -> outln(PDL)
extern "C" void kernel_launch(void* const* d_in, const int* in_sizes, int n_in,
                              void* d_out, int out_size) {
    const float* means      = (const float*)d_in[0];
    const float* feature    = (const float*)d_in[1];
    const float* feat0      = (const float*)d_in[2];
    const float* feat1      = (const float*)d_in[3];
    const float* feat2      = (const float*)d_in[4];
    const float* cam2ego    = (const float*)d_in[5];
    const float* intrins    = (const float*)d_in[6];
    const float* post_rots  = (const float*)d_in[7];
    const float* post_trans = (const float*)d_in[8];
    const float* W_off      = (const float*)d_in[9];
    const float* b_off      = (const float*)d_in[10];
    const float* W_attn     = (const float*)d_in[11];
    const float* b_attn     = (const float*)d_in[12];
    const float* W_val      = (const float*)d_in[13];
    const float* b_val      = (const float*)d_in[14];
    const float* W_out      = (const float*)d_in[15];
    const float* b_out      = (const float*)d_in[16];
    const float* ce         = (const float*)d_in[17];
    const float* le         = (const float*)d_in[18];
    const float* ln_g       = (const float*)d_in[19];
    const float* ln_b       = (const float*)d_in[20];
    float* out = (float*)d_out;

    cudaStream_t s1;
    cudaEvent_t ePrep, eValue;
    cudaStreamCreateWithFlags(&s1, cudaStreamNonBlocking);
    cudaEventCreateWithFlags(&ePrep,  cudaEventDisableTiming);
    cudaEventCreateWithFlags(&eValue, cudaEventDisableTiming);

    // 1) prep (+projinv) on main
    k_prep<<<440, 256>>>(W_val, W_off, W_attn, W_out, ce, le,
                         cam2ego, means, intrins, post_rots, post_trans);
    cudaEventRecord(ePrep, 0);

    // 2) value on s1 (after prep), offattn on main
    cudaStreamWaitEvent(s1, ePrep, 0);
    k_value<<<1386, 256, 0, s1>>>(feat0, feat1, feat2, b_val);
    cudaEventRecord(eValue, s1);

    k_offattn<<<dim3(100, 3), 256>>>(feature, b_off, b_attn);

    // 3) join: gather, then outln with PDL (prologue overlaps gather tail)
    cudaStreamWaitEvent(0, eValue, 0);
    k_gather<<<NQ, 256>>>();

    {
        cudaLaunchConfig_t cfg = {};
        cfg.gridDim = dim3(100, 1, 1);
        cfg.blockDim = dim3(256, 1, 1);
        cfg.dynamicSmemBytes = 0;
        cfg.stream = 0;
        cudaLaunchAttribute attr[1];
        attr[0].id = cudaLaunchAttributeProgrammaticStreamSerialization;
        attr[0].val.programmaticStreamSerializationAllowed = 1;
        cfg.attrs = attr;
        cfg.numAttrs = 1;
        cudaLaunchKernelEx(&cfg, k_outln, feature, b_out, ln_g, ln_b, out);
    }
}